// round 13
// baseline (speedup 1.0000x reference)
#include <cuda_runtime.h>
#include <math.h>
#include <stdint.h>

#define KSZ 7
#define PAD 3

#define B_  8
#define T_  16
#define C_  256
#define HW_ 784
#define HW4_ 196                  // float4 per full slice
#define PSROW (T_ + 2 * PAD + 1)  // 23

#define HHW4 98                   // float4 per half slice (main tile)
#define HBYTES 1568
#define POOLROWS 8
#define POOLTILE_B (POOLROWS * HW_ * 4)   // 25088

// items per batch: 512 pool tiles + 65 coeff + 512 main tiles
#define SEG 1089
#define NITEMS (B_ * SEG)         // 8712

// dynamic smem layout
#define OFF_DATA 0                // 25088 B (pool tile / main tile) or coeff ps (23552)
#define OFF_W1   23552            // coeff w1s: 512 f
#define OFF_W2   (OFF_W1 + 2048)  // coeff w2s: 224 f
#define OFF_RED  (OFF_W2 + 896)   // coeff red: 64 f -> ends 26752
#define OFF_LRS  26752            // main gates: 16 f
#define OFF_MBAR 26816
#define DYN_SMEM 26880

__device__ float d_pooled[B_ * C_ * T_];      // [b][c][t]
__device__ float d_Kern[B_ * C_ * KSZ];       // [b][c][k]
__device__ float d_Yt[B_ * T_ * 64];          // [b][t][o]
__device__ int   d_sched[17];                 // [0]=ticket, [1..8]=pool_done, [9..16]=coeff_done

// ---------------- PTX helpers ----------------
__device__ __forceinline__ uint32_t smem_u32(const void* p) {
    return (uint32_t)__cvta_generic_to_shared(p);
}
#define MBAR_INIT(a, n) \
    asm volatile("mbarrier.init.shared.b64 [%0], %1;" :: "r"(a), "r"(n) : "memory")
#define MBAR_EXPECT(a, bytes) \
    asm volatile("mbarrier.arrive.expect_tx.shared.b64 _, [%0], %1;" :: "r"(a), "r"(bytes) : "memory")
#define MBAR_WAIT(a, ph) do {                                                   \
    uint32_t _done = 0;                                                         \
    while (!_done) {                                                            \
        asm volatile("{\n\t.reg .pred p;\n\t"                                   \
            "mbarrier.try_wait.parity.acquire.cta.shared::cta.b64 p, [%1], %2, 0x989680;\n\t" \
            "selp.b32 %0, 1, 0, p;\n\t}"                                        \
            : "=r"(_done) : "r"(a), "r"(ph) : "memory");                        \
    }                                                                           \
} while (0)
#define BULK_G2S(dst_s, src_g, bytes, mbar) \
    asm volatile("cp.async.bulk.shared::cluster.global.mbarrier::complete_tx::bytes [%0], [%1], %2, [%3];" \
        :: "r"(dst_s), "l"(src_g), "r"(bytes), "r"(mbar) : "memory")
#define BULK_S2G(dst_g, src_s, bytes) \
    asm volatile("cp.async.bulk.global.shared::cta.bulk_group [%0], [%1], %2;" \
        :: "l"(dst_g), "r"(src_s), "r"(bytes) : "memory")
#define BULK_COMMIT() asm volatile("cp.async.bulk.commit_group;" ::: "memory")
#define BULK_WAIT0()  asm volatile("cp.async.bulk.wait_group 0;" ::: "memory")
#define FENCE_ASYNC() asm volatile("fence.proxy.async;" ::: "memory")

__global__ void init_kernel() {
    if (threadIdx.x < 17) d_sched[threadIdx.x] = 0;
}

// ---------------------------------------------------------------------------
// Persistent scheduler kernel.
// ---------------------------------------------------------------------------
__global__ void __launch_bounds__(128)
tam_sched_kernel(const float* __restrict__ x, float* __restrict__ out,
                 const float* __restrict__ W1, const float* __restrict__ W2,
                 const float* __restrict__ Wl1, const float* __restrict__ Wl2)
{
    extern __shared__ __align__(128) char smem[];
    float4* sm4  = reinterpret_cast<float4*>(smem);
    float*  smf  = reinterpret_cast<float*>(smem);
    float*  w1s  = reinterpret_cast<float*>(smem + OFF_W1);
    float*  w2s  = reinterpret_cast<float*>(smem + OFF_W2);
    float*  redp = reinterpret_cast<float*>(smem + OFF_RED);
    float*  lrs  = reinterpret_cast<float*>(smem + OFF_LRS);
    const uint32_t mbar   = smem_u32(smem + OFF_MBAR);
    const uint32_t s_base = smem_u32(smem);
    __shared__ int s_ticket;

    const int tid  = threadIdx.x;      // 0..127
    const int warp = tid >> 5;
    const int lane = tid & 31;

    if (tid == 0) MBAR_INIT(mbar, 1);
    __syncthreads();
    int mb_phase = 0;

    for (;;) {
        __syncthreads();
        if (tid == 0) s_ticket = atomicAdd(&d_sched[0], 1);
        __syncthreads();
        const int item = s_ticket;
        if (item >= NITEMS) break;

        const int b = item / SEG;
        const int r = item - b * SEG;

        if (r < 512) {
            // ---------------- POOL tile: 8 rows, one 25088B bulk load -------
            const int row0 = b * (T_ * C_) + r * POOLROWS;
            if (tid == 0) {
                MBAR_EXPECT(mbar, (uint32_t)POOLTILE_B);
                BULK_G2S(s_base, x + (size_t)row0 * HW_, (uint32_t)POOLTILE_B, mbar);
            }
            MBAR_WAIT(mbar, mb_phase);
            mb_phase ^= 1;

            #pragma unroll
            for (int rr = 0; rr < 2; rr++) {
                const int lrow = warp * 2 + rr;
                const float4* base = sm4 + lrow * HW4_;
                float s = 0.f;
                #pragma unroll 7
                for (int i = lane; i < HW4_; i += 32) {
                    float4 v = base[i];
                    s += (v.x + v.y) + (v.z + v.w);
                }
                #pragma unroll
                for (int o = 16; o > 0; o >>= 1) s += __shfl_xor_sync(0xffffffffu, s, o);
                if (lane == 0) {
                    int row = row0 + lrow;       // (b*T + t)*C + c
                    int c = row & (C_ - 1);
                    int t = (row >> 8) & (T_ - 1);
                    d_pooled[(b * C_ + c) * T_ + t] = s * (1.0f / (float)HW_);
                }
            }
            __threadfence();
            __syncthreads();
            if (tid == 0) atomicAdd(&d_sched[1 + b], 1);

        } else if (r < 577) {
            // ---------------- COEFF item o = r-512 (64 = G branch) ----------
            const int o = r - 512;
            if (tid == 0) {
                while (((volatile int*)d_sched)[1 + b] < 512) __nanosleep(64);
                __threadfence();
            }
            __syncthreads();

            if (o == 64) {
                for (int i = tid; i < 512; i += 128) w1s[i] = W1[i];
                for (int i = tid; i < 224; i += 128) w2s[i] = W2[i];
                __syncthreads();
                #pragma unroll
                for (int cc = 0; cc < 2; cc++) {
                    const int c = tid + cc * 128;
                    float p[T_];
                    const float4* pp = reinterpret_cast<const float4*>(d_pooled + (b * C_ + c) * T_);
                    #pragma unroll
                    for (int q = 0; q < 4; q++) {
                        float4 v = pp[q];
                        p[q*4+0]=v.x; p[q*4+1]=v.y; p[q*4+2]=v.z; p[q*4+3]=v.w;
                    }
                    float s[KSZ];
                    #pragma unroll
                    for (int k = 0; k < KSZ; k++) s[k] = 0.f;
                    for (int u = 0; u < 32; u++) {
                        float acc = 0.f;
                        #pragma unroll
                        for (int t = 0; t < T_; t++) acc += p[t] * w1s[u * 16 + t];
                        float g = tanhf(acc);
                        #pragma unroll
                        for (int k = 0; k < KSZ; k++) s[k] += g * w2s[k * 32 + u];
                    }
                    float m = s[0];
                    #pragma unroll
                    for (int k = 1; k < KSZ; k++) m = fmaxf(m, s[k]);
                    float e[KSZ], sum = 0.f;
                    #pragma unroll
                    for (int k = 0; k < KSZ; k++) { e[k] = expf(s[k] - m); sum += e[k]; }
                    float inv = 1.0f / sum;
                    #pragma unroll
                    for (int k = 0; k < KSZ; k++)
                        d_Kern[(b * C_ + c) * KSZ + k] = e[k] * inv;
                }
            } else {
                // conv1d output channel o
                for (int i = tid; i < C_ * PSROW; i += 128) smf[i] = 0.f;
                __syncthreads();
                const float4* pp = reinterpret_cast<const float4*>(d_pooled + b * C_ * T_);
                for (int i = tid; i < C_ * T_ / 4; i += 128) {
                    float4 v = pp[i];
                    int e0 = i * 4;
                    int c = e0 >> 4, t = e0 & 15;
                    float* rr = &smf[c * PSROW + PAD + t];
                    rr[0] = v.x; rr[1] = v.y; rr[2] = v.z; rr[3] = v.w;
                }
                __syncthreads();

                float acc[T_];
                #pragma unroll
                for (int t = 0; t < T_; t++) acc[t] = 0.f;
                const float* w = Wl1 + o * (C_ * KSZ);
                #pragma unroll
                for (int ii = 0; ii < 2; ii++) {
                    const int i = tid * 2 + ii;
                    float wk[KSZ];
                    #pragma unroll
                    for (int k = 0; k < KSZ; k++) wk[k] = w[i * KSZ + k];
                    float pv[T_ + 2 * PAD];
                    #pragma unroll
                    for (int j = 0; j < T_ + 2 * PAD; j++) pv[j] = smf[i * PSROW + j];
                    #pragma unroll
                    for (int t = 0; t < T_; t++) {
                        #pragma unroll
                        for (int k = 0; k < KSZ; k++)
                            acc[t] += wk[k] * pv[t + k];
                    }
                }
                #pragma unroll
                for (int off = 16; off > 0; off >>= 1) {
                    #pragma unroll
                    for (int t = 0; t < T_; t++)
                        acc[t] += __shfl_xor_sync(0xffffffffu, acc[t], off);
                }
                __syncthreads();   // smf reuse barrier
                if (lane == 0) {
                    #pragma unroll
                    for (int t = 0; t < T_; t++) redp[warp * T_ + t] = acc[t];
                }
                __syncthreads();
                if (tid < T_) {
                    float s = redp[0*T_+tid] + redp[1*T_+tid] + redp[2*T_+tid] + redp[3*T_+tid];
                    d_Yt[(b * T_ + tid) * 64 + o] = tanhf(s);
                }
            }
            __threadfence();
            __syncthreads();
            if (tid == 0) atomicAdd(&d_sched[9 + b], 1);

        } else {
            // ---------------- MAIN tile id = r-577: (c, half) ---------------
            const int id   = r - 577;
            const int c    = id >> 1;
            const int half = id & 1;
            const int bc   = b * C_ + c;
            const size_t row0 = (size_t)(b * T_ * C_ + c);
            const size_t goff = row0 * HW_ + half * (HHW4 * 4);

            // issue x loads first (no dependency), then wait for coeff
            if (tid == 0) {
                MBAR_EXPECT(mbar, (uint32_t)(T_ * HBYTES));
                #pragma unroll
                for (int t = 0; t < T_; t++)
                    BULK_G2S(s_base + t * HBYTES,
                             x + goff + (size_t)t * (C_ * HW_),
                             (uint32_t)HBYTES, mbar);
                while (((volatile int*)d_sched)[9 + b] < 65) __nanosleep(64);
                __threadfence();
            }
            __syncthreads();

            if (tid < T_) {
                const float4* wv = reinterpret_cast<const float4*>(Wl2 + c * 64);
                const float4* yv = reinterpret_cast<const float4*>(d_Yt + (b * T_ + tid) * 64);
                float acc = 0.f;
                #pragma unroll
                for (int q = 0; q < 16; q++) {
                    float4 wq = wv[q], yq = yv[q];
                    acc += wq.x * yq.x + wq.y * yq.y + wq.z * yq.z + wq.w * yq.w;
                }
                lrs[tid] = 1.0f / (1.0f + expf(-acc));
            }
            float kr[KSZ];
            #pragma unroll
            for (int k = 0; k < KSZ; k++) kr[k] = d_Kern[bc * KSZ + k];
            __syncthreads();

            MBAR_WAIT(mbar, mb_phase);
            mb_phase ^= 1;

            if (tid < HHW4) {
                float4 g[T_];
                #pragma unroll
                for (int t = 0; t < T_; t++) {
                    float4 v = sm4[t * HHW4 + tid];
                    float l = lrs[t];
                    g[t].x = v.x * l; g[t].y = v.y * l; g[t].z = v.z * l; g[t].w = v.w * l;
                }
                #pragma unroll
                for (int t = 0; t < T_; t++) {
                    float4 a; a.x = a.y = a.z = a.w = 0.f;
                    #pragma unroll
                    for (int k = 0; k < KSZ; k++) {
                        int u = t + k - PAD;
                        if (u >= 0 && u < T_) {
                            float kk = kr[k];
                            a.x += kk * g[u].x;
                            a.y += kk * g[u].y;
                            a.z += kk * g[u].z;
                            a.w += kk * g[u].w;
                        }
                    }
                    sm4[t * HHW4 + tid] = a;
                }
            }
            __syncthreads();
            if (tid == 0) {
                FENCE_ASYNC();
                #pragma unroll
                for (int t = 0; t < T_; t++)
                    BULK_S2G(out + goff + (size_t)t * (C_ * HW_),
                             s_base + t * HBYTES, (uint32_t)HBYTES);
                BULK_COMMIT();
                BULK_WAIT0();
            }
            __syncthreads();   // no thread proceeds with bulk stores in flight
        }
    }
}

// ---------------------------------------------------------------------------
extern "C" void kernel_launch(void* const* d_in, const int* in_sizes, int n_in,
                              void* d_out, int out_size) {
    const float* x   = (const float*)d_in[0];
    const float* W1  = (const float*)d_in[1];
    const float* W2  = (const float*)d_in[2];
    const float* Wl1 = (const float*)d_in[3];
    const float* Wl2 = (const float*)d_in[4];
    float* out = (float*)d_out;

    static bool attr_done = false;
    if (!attr_done) {
        cudaFuncSetAttribute(tam_sched_kernel,
            cudaFuncAttributeMaxDynamicSharedMemorySize, DYN_SMEM);
        attr_done = true;
    }

    init_kernel<<<1, 32>>>();
    tam_sched_kernel<<<148 * 8, 128, DYN_SMEM>>>(x, out, W1, W2, Wl1, Wl2);
}

// round 14
// speedup vs baseline: 1.3688x; 1.3688x over previous
#include <cuda_runtime.h>
#include <math.h>
#include <stdint.h>

#define KSZ 7
#define PAD 3

#define B_  8
#define T_  16
#define C_  256
#define HW_ 784
#define HW4_ 196                  // float4 per full slice
#define PSROW (T_ + 2 * PAD + 1)  // 23

#define HHW4 98                   // float4 per half slice (main tile)
#define HBYTES 1568

#define POOLROWS 8
#define POOLTILE_B (POOLROWS * HW_ * 4)   // 25088
#define POOL_SMEM (POOLTILE_B + 16)

// fused kernel dynamic smem layout (union of coeff + main needs)
#define OFF_W1   23552            // coeff w1s: 512 f  (after ps[C_*PSROW]=23552B)
#define OFF_W2   (OFF_W1 + 2048)  // coeff w2s: 224 f
#define OFF_RED  (OFF_W2 + 896)   // coeff red: 64 f  -> ends 26752
#define OFF_LRS  26752            // main gates: 16 f
#define OFF_MBAR 26816
#define DYN_SMEM 26880

#define NCOEFF (B_ * 65)          // 520
#define NMAIN  (B_ * 512)         // 4096

__device__ float d_pooled[B_ * C_ * T_];      // [b][c][t]
__device__ float d_Kern[B_ * C_ * KSZ];       // [b][c][k]
__device__ float d_Yt[B_ * T_ * 64];          // [b][t][o]
__device__ int   d_cdone[B_];                 // coeff-done counters

// ---------------- PTX helpers ----------------
__device__ __forceinline__ uint32_t smem_u32(const void* p) {
    return (uint32_t)__cvta_generic_to_shared(p);
}
#define MBAR_INIT(a, n) \
    asm volatile("mbarrier.init.shared.b64 [%0], %1;" :: "r"(a), "r"(n) : "memory")
#define MBAR_EXPECT(a, bytes) \
    asm volatile("mbarrier.arrive.expect_tx.shared.b64 _, [%0], %1;" :: "r"(a), "r"(bytes) : "memory")
#define MBAR_WAIT(a, ph) do {                                                   \
    uint32_t _done = 0;                                                         \
    while (!_done) {                                                            \
        asm volatile("{\n\t.reg .pred p;\n\t"                                   \
            "mbarrier.try_wait.parity.acquire.cta.shared::cta.b64 p, [%1], %2, 0x989680;\n\t" \
            "selp.b32 %0, 1, 0, p;\n\t}"                                        \
            : "=r"(_done) : "r"(a), "r"(ph) : "memory");                        \
    }                                                                           \
} while (0)
#define BULK_G2S(dst_s, src_g, bytes, mbar) \
    asm volatile("cp.async.bulk.shared::cluster.global.mbarrier::complete_tx::bytes [%0], [%1], %2, [%3];" \
        :: "r"(dst_s), "l"(src_g), "r"(bytes), "r"(mbar) : "memory")
#define BULK_S2G(dst_g, src_s, bytes) \
    asm volatile("cp.async.bulk.global.shared::cta.bulk_group [%0], [%1], %2;" \
        :: "l"(dst_g), "r"(src_s), "r"(bytes) : "memory")
#define BULK_COMMIT() asm volatile("cp.async.bulk.commit_group;" ::: "memory")
#define BULK_WAIT0()  asm volatile("cp.async.bulk.wait_group 0;" ::: "memory")
#define FENCE_ASYNC() asm volatile("fence.proxy.async;" ::: "memory")

// ---------------------------------------------------------------------------
// Kernel 1: pool. 4096 blocks x 256 threads, 8-row (25 KB) TMA tiles for
// 8 CTAs/SM. Block 0 also zeroes the coeff counters (completes before the
// fused launch starts — launch ordering guarantees visibility).
// ---------------------------------------------------------------------------
__global__ void __launch_bounds__(256)
pool_kernel(const float* __restrict__ x) {
    extern __shared__ __align__(128) char smem[];
    float4* sm4 = reinterpret_cast<float4*>(smem);
    const uint32_t mbar = smem_u32(smem + POOLTILE_B);

    const int tid  = threadIdx.x;
    const int warp = tid >> 5;
    const int lane = tid & 31;
    const int row0 = blockIdx.x * POOLROWS;      // global row

    if (blockIdx.x == 0 && tid < B_) d_cdone[tid] = 0;

    if (tid == 0) MBAR_INIT(mbar, 1);
    __syncthreads();
    if (tid == 0) {
        MBAR_EXPECT(mbar, (uint32_t)POOLTILE_B);
        BULK_G2S(smem_u32(smem), x + (size_t)row0 * HW_, (uint32_t)POOLTILE_B, mbar);
    }
    MBAR_WAIT(mbar, 0);

    const float4* r = sm4 + warp * HW4_;         // warp per row
    float s = 0.f;
    #pragma unroll 7
    for (int i = lane; i < HW4_; i += 32) {
        float4 v = r[i];
        s += (v.x + v.y) + (v.z + v.w);
    }
    #pragma unroll
    for (int o = 16; o > 0; o >>= 1) s += __shfl_xor_sync(0xffffffffu, s, o);

    if (lane == 0) {
        int row = row0 + warp;                   // (b*T + t)*C + c
        int c  = row & (C_ - 1);
        int bt = row >> 8;
        int t  = bt & (T_ - 1);
        int b  = bt >> 4;
        d_pooled[(b * C_ + c) * T_ + t] = s * (1.0f / (float)HW_);
    }
}

// ---------------------------------------------------------------------------
// Kernel 2: fused coeff + main. 4616 blocks x 128 threads.
//   bid < 520  : coeff block (b = bid/65, o = bid%65); increments d_cdone[b].
//   bid >= 520 : main half-slice tile; issues its 16 TMA x-loads FIRST, then
//                spins on d_cdone[b]==65 (loads overlap coeff compute).
// ---------------------------------------------------------------------------
__global__ void __launch_bounds__(128)
fused_kernel(const float* __restrict__ x, float* __restrict__ out,
             const float* __restrict__ W1, const float* __restrict__ W2,
             const float* __restrict__ Wl1, const float* __restrict__ Wl2)
{
    extern __shared__ __align__(128) char smem[];
    float4* sm4  = reinterpret_cast<float4*>(smem);
    float*  smf  = reinterpret_cast<float*>(smem);
    float*  w1s  = reinterpret_cast<float*>(smem + OFF_W1);
    float*  w2s  = reinterpret_cast<float*>(smem + OFF_W2);
    float*  redp = reinterpret_cast<float*>(smem + OFF_RED);
    float*  lrs  = reinterpret_cast<float*>(smem + OFF_LRS);
    const uint32_t mbar   = smem_u32(smem + OFF_MBAR);
    const uint32_t s_base = smem_u32(smem);

    const int bid  = blockIdx.x;
    const int tid  = threadIdx.x;      // 0..127
    const int warp = tid >> 5;
    const int lane = tid & 31;

    if (bid < NCOEFF) {
        // ================= COEFF =================
        const int b = bid / 65;
        const int o = bid - b * 65;

        if (o == 64) {
            // ---- G branch: 2 channels per thread ----
            for (int i = tid; i < 512; i += 128) w1s[i] = W1[i];
            for (int i = tid; i < 224; i += 128) w2s[i] = W2[i];
            __syncthreads();
            #pragma unroll
            for (int cc = 0; cc < 2; cc++) {
                const int c = tid + cc * 128;
                float p[T_];
                const float4* pp = reinterpret_cast<const float4*>(d_pooled + (b * C_ + c) * T_);
                #pragma unroll
                for (int q = 0; q < 4; q++) {
                    float4 v = pp[q];
                    p[q*4+0]=v.x; p[q*4+1]=v.y; p[q*4+2]=v.z; p[q*4+3]=v.w;
                }
                float s[KSZ];
                #pragma unroll
                for (int k = 0; k < KSZ; k++) s[k] = 0.f;
                for (int u = 0; u < 32; u++) {
                    float acc = 0.f;
                    #pragma unroll
                    for (int t = 0; t < T_; t++) acc += p[t] * w1s[u * 16 + t];
                    float g = tanhf(acc);
                    #pragma unroll
                    for (int k = 0; k < KSZ; k++) s[k] += g * w2s[k * 32 + u];
                }
                float m = s[0];
                #pragma unroll
                for (int k = 1; k < KSZ; k++) m = fmaxf(m, s[k]);
                float e[KSZ], sum = 0.f;
                #pragma unroll
                for (int k = 0; k < KSZ; k++) { e[k] = expf(s[k] - m); sum += e[k]; }
                float inv = 1.0f / sum;
                #pragma unroll
                for (int k = 0; k < KSZ; k++)
                    d_Kern[(b * C_ + c) * KSZ + k] = e[k] * inv;
            }
        } else {
            // ---- L-branch conv1d, output channel o ----
            for (int i = tid; i < C_ * PSROW; i += 128) smf[i] = 0.f;
            __syncthreads();
            const float4* pp = reinterpret_cast<const float4*>(d_pooled + b * C_ * T_);
            for (int i = tid; i < C_ * T_ / 4; i += 128) {
                float4 v = pp[i];
                int e0 = i * 4;
                int c = e0 >> 4, t = e0 & 15;
                float* rr = &smf[c * PSROW + PAD + t];
                rr[0] = v.x; rr[1] = v.y; rr[2] = v.z; rr[3] = v.w;
            }
            __syncthreads();

            float acc[T_];
            #pragma unroll
            for (int t = 0; t < T_; t++) acc[t] = 0.f;
            const float* w = Wl1 + o * (C_ * KSZ);
            #pragma unroll
            for (int ii = 0; ii < 2; ii++) {
                const int i = tid * 2 + ii;
                float wk[KSZ];
                #pragma unroll
                for (int k = 0; k < KSZ; k++) wk[k] = w[i * KSZ + k];
                float pv[T_ + 2 * PAD];
                #pragma unroll
                for (int j = 0; j < T_ + 2 * PAD; j++) pv[j] = smf[i * PSROW + j];
                #pragma unroll
                for (int t = 0; t < T_; t++) {
                    #pragma unroll
                    for (int k = 0; k < KSZ; k++)
                        acc[t] += wk[k] * pv[t + k];
                }
            }
            #pragma unroll
            for (int off = 16; off > 0; off >>= 1) {
                #pragma unroll
                for (int t = 0; t < T_; t++)
                    acc[t] += __shfl_xor_sync(0xffffffffu, acc[t], off);
            }
            if (lane == 0) {
                #pragma unroll
                for (int t = 0; t < T_; t++) redp[warp * T_ + t] = acc[t];
            }
            __syncthreads();
            if (tid < T_) {
                float s = redp[0*T_+tid] + redp[1*T_+tid] + redp[2*T_+tid] + redp[3*T_+tid];
                d_Yt[(b * T_ + tid) * 64 + o] = tanhf(s);
            }
        }
        __threadfence();
        __syncthreads();
        if (tid == 0) atomicAdd(&d_cdone[b], 1);
        return;
    }

    // ================= MAIN half-slice tile =================
    const int id   = bid - NCOEFF;      // 0..4095
    const int b    = id >> 9;           // /512
    const int r    = id & 511;
    const int c    = r >> 1;
    const int half = r & 1;
    const int bc   = b * C_ + c;

    const size_t row0 = (size_t)(b * T_ * C_ + c);
    const size_t goff = row0 * HW_ + half * (HHW4 * 4);

    if (tid == 0) MBAR_INIT(mbar, 1);
    __syncthreads();
    if (tid == 0) {
        // issue all x loads FIRST — they overlap the coeff blocks' compute
        MBAR_EXPECT(mbar, (uint32_t)(T_ * HBYTES));
        #pragma unroll
        for (int t = 0; t < T_; t++)
            BULK_G2S(s_base + t * HBYTES,
                     x + goff + (size_t)t * (C_ * HW_),
                     (uint32_t)HBYTES, mbar);
        // then wait for this batch's coefficients
        while (((volatile int*)d_cdone)[b] < 65) __nanosleep(64);
        __threadfence();
    }
    __syncthreads();

    if (tid < T_) {
        const float4* wv = reinterpret_cast<const float4*>(Wl2 + c * 64);
        const float4* yv = reinterpret_cast<const float4*>(d_Yt + (b * T_ + tid) * 64);
        float acc = 0.f;
        #pragma unroll
        for (int q = 0; q < 16; q++) {
            float4 wq = wv[q], yq = yv[q];
            acc += wq.x * yq.x + wq.y * yq.y + wq.z * yq.z + wq.w * yq.w;
        }
        lrs[tid] = 1.0f / (1.0f + expf(-acc));
    }
    float kr[KSZ];
    #pragma unroll
    for (int k = 0; k < KSZ; k++) kr[k] = d_Kern[bc * KSZ + k];
    __syncthreads();

    MBAR_WAIT(mbar, 0);

    if (tid < HHW4) {
        float4 g[T_];
        #pragma unroll
        for (int t = 0; t < T_; t++) {
            float4 v = sm4[t * HHW4 + tid];
            float l = lrs[t];
            g[t].x = v.x * l; g[t].y = v.y * l; g[t].z = v.z * l; g[t].w = v.w * l;
        }
        #pragma unroll
        for (int t = 0; t < T_; t++) {
            float4 a; a.x = a.y = a.z = a.w = 0.f;
            #pragma unroll
            for (int k = 0; k < KSZ; k++) {
                int u = t + k - PAD;
                if (u >= 0 && u < T_) {          // constant-folded
                    float kk = kr[k];
                    a.x += kk * g[u].x;
                    a.y += kk * g[u].y;
                    a.z += kk * g[u].z;
                    a.w += kk * g[u].w;
                }
            }
            sm4[t * HHW4 + tid] = a;
        }
    }
    __syncthreads();
    if (tid == 0) {
        FENCE_ASYNC();
        #pragma unroll
        for (int t = 0; t < T_; t++)
            BULK_S2G(out + goff + (size_t)t * (C_ * HW_),
                     s_base + t * HBYTES, (uint32_t)HBYTES);
        BULK_COMMIT();
        BULK_WAIT0();
    }
    __syncthreads();   // load-bearing: no thread exits with bulk stores in flight
}

// ---------------------------------------------------------------------------
extern "C" void kernel_launch(void* const* d_in, const int* in_sizes, int n_in,
                              void* d_out, int out_size) {
    const float* x   = (const float*)d_in[0];
    const float* W1  = (const float*)d_in[1];
    const float* W2  = (const float*)d_in[2];
    const float* Wl1 = (const float*)d_in[3];
    const float* Wl2 = (const float*)d_in[4];
    float* out = (float*)d_out;

    static bool attr_done = false;
    if (!attr_done) {
        cudaFuncSetAttribute(pool_kernel,
            cudaFuncAttributeMaxDynamicSharedMemorySize, POOL_SMEM);
        cudaFuncSetAttribute(fused_kernel,
            cudaFuncAttributeMaxDynamicSharedMemorySize, DYN_SMEM);
        attr_done = true;
    }

    pool_kernel<<<(B_ * T_ * C_) / POOLROWS, 256, POOL_SMEM>>>(x);
    fused_kernel<<<NCOEFF + NMAIN, 128, DYN_SMEM>>>(x, out, W1, W2, Wl1, Wl2);
}

// round 17
// speedup vs baseline: 1.5292x; 1.1171x over previous
#include <cuda_runtime.h>
#include <math.h>
#include <stdint.h>

#define KSZ 7
#define PAD 3

#define B_  8
#define T_  16
#define C_  256
#define HW_ 784
#define HW4_ 196                  // float4 per full slice
#define PSROW (T_ + 2 * PAD + 1)  // 23

#define HHW4 98                   // float4 per half slice (main tile)
#define HBYTES 1568

#define POOLROWS 8
#define POOLTILE_B (POOLROWS * HW_ * 4)   // 25088
#define POOL_SMEM (POOLTILE_B + 16)
#define NPOOLBLK ((B_ * T_ * C_) / POOLROWS)   // 4096

// fused kernel dynamic smem layout (union of coeff + main needs)
#define OFF_W1   23552
#define OFF_W2   (OFF_W1 + 2048)
#define OFF_RED  (OFF_W2 + 896)
#define OFF_LRS  26752
#define OFF_MBAR 26816
#define DYN_SMEM 26880

#define NCOEFF (B_ * 65)          // 520
#define NMAIN  (B_ * 512)         // 4096

__device__ float d_pooled[B_ * C_ * T_];      // [b][c][t]
__device__ float d_Kern[B_ * C_ * KSZ];       // [b][c][k]
__device__ float d_Yt[B_ * T_ * 64];          // [b][t][o]
__device__ int   d_cdone[B_];                 // coeff-done counters

// ---------------- PTX helpers ----------------
__device__ __forceinline__ uint32_t smem_u32(const void* p) {
    return (uint32_t)__cvta_generic_to_shared(p);
}
#define MBAR_INIT(a, n) \
    asm volatile("mbarrier.init.shared.b64 [%0], %1;" :: "r"(a), "r"(n) : "memory")
#define MBAR_EXPECT(a, bytes) \
    asm volatile("mbarrier.arrive.expect_tx.shared.b64 _, [%0], %1;" :: "r"(a), "r"(bytes) : "memory")
#define MBAR_WAIT(a, ph) do {                                                   \
    uint32_t _done = 0;                                                         \
    while (!_done) {                                                            \
        asm volatile("{\n\t.reg .pred p;\n\t"                                   \
            "mbarrier.try_wait.parity.acquire.cta.shared::cta.b64 p, [%1], %2, 0x989680;\n\t" \
            "selp.b32 %0, 1, 0, p;\n\t}"                                        \
            : "=r"(_done) : "r"(a), "r"(ph) : "memory");                        \
    }                                                                           \
} while (0)
#define BULK_G2S(dst_s, src_g, bytes, mbar) \
    asm volatile("cp.async.bulk.shared::cluster.global.mbarrier::complete_tx::bytes [%0], [%1], %2, [%3];" \
        :: "r"(dst_s), "l"(src_g), "r"(bytes), "r"(mbar) : "memory")
#define BULK_S2G(dst_g, src_s, bytes) \
    asm volatile("cp.async.bulk.global.shared::cta.bulk_group [%0], [%1], %2;" \
        :: "l"(dst_g), "r"(src_s), "r"(bytes) : "memory")
#define BULK_COMMIT() asm volatile("cp.async.bulk.commit_group;" ::: "memory")
#define BULK_WAIT0()  asm volatile("cp.async.bulk.wait_group 0;" ::: "memory")
#define FENCE_ASYNC() asm volatile("fence.proxy.async;" ::: "memory")

// ---------------------------------------------------------------------------
// Kernel 1: pool, REVERSED block->row map. Block i processes rows of batch
// (7 - ...) — i.e., batch 7 is read first, batch 0 LAST, so batch 0's x is
// the freshest in L2 when the fused kernel's main tiles (batch-ascending)
// start reading. Block handling the LAST rows also zeroes d_cdone.
// ---------------------------------------------------------------------------
__global__ void __launch_bounds__(256)
pool_kernel(const float* __restrict__ x) {
    extern __shared__ __align__(128) char smem[];
    float4* sm4 = reinterpret_cast<float4*>(smem);
    const uint32_t mbar = smem_u32(smem + POOLTILE_B);

    const int tid  = threadIdx.x;
    const int warp = tid >> 5;
    const int lane = tid & 31;
    // reversed mapping: blockIdx 0 -> highest rows (batch 7), last block -> rows 0..7
    const int row0 = (NPOOLBLK - 1 - blockIdx.x) * POOLROWS;

    if (blockIdx.x == 0 && tid < B_) d_cdone[tid] = 0;

    if (tid == 0) MBAR_INIT(mbar, 1);
    __syncthreads();
    if (tid == 0) {
        MBAR_EXPECT(mbar, (uint32_t)POOLTILE_B);
        BULK_G2S(smem_u32(smem), x + (size_t)row0 * HW_, (uint32_t)POOLTILE_B, mbar);
    }
    MBAR_WAIT(mbar, 0);

    const float4* r = sm4 + warp * HW4_;         // warp per row
    float s = 0.f;
    #pragma unroll 7
    for (int i = lane; i < HW4_; i += 32) {
        float4 v = r[i];
        s += (v.x + v.y) + (v.z + v.w);
    }
    #pragma unroll
    for (int o = 16; o > 0; o >>= 1) s += __shfl_xor_sync(0xffffffffu, s, o);

    if (lane == 0) {
        int row = row0 + warp;                   // (b*T + t)*C + c
        int c  = row & (C_ - 1);
        int bt = row >> 8;
        int t  = bt & (T_ - 1);
        int b  = bt >> 4;
        d_pooled[(b * C_ + c) * T_ + t] = s * (1.0f / (float)HW_);
    }
}

// ---------------------------------------------------------------------------
// Kernel 2: fused coeff + main (identical to the PASSING R14 version).
//   bid < 520  : coeff block (never waits; pool completed in prior launch).
//   bid >= 520 : main half-slice tile; issues 16 TMA x-loads first, then
//                spins on d_cdone[b]==65. Single spin level, dep produced by
//                blocks that never wait — proven-safe pattern.
// ---------------------------------------------------------------------------
__global__ void __launch_bounds__(128)
fused_kernel(const float* __restrict__ x, float* __restrict__ out,
             const float* __restrict__ W1, const float* __restrict__ W2,
             const float* __restrict__ Wl1, const float* __restrict__ Wl2)
{
    extern __shared__ __align__(128) char smem[];
    float4* sm4  = reinterpret_cast<float4*>(smem);
    float*  smf  = reinterpret_cast<float*>(smem);
    float*  w1s  = reinterpret_cast<float*>(smem + OFF_W1);
    float*  w2s  = reinterpret_cast<float*>(smem + OFF_W2);
    float*  redp = reinterpret_cast<float*>(smem + OFF_RED);
    float*  lrs  = reinterpret_cast<float*>(smem + OFF_LRS);
    const uint32_t mbar   = smem_u32(smem + OFF_MBAR);
    const uint32_t s_base = smem_u32(smem);

    const int bid  = blockIdx.x;
    const int tid  = threadIdx.x;      // 0..127
    const int warp = tid >> 5;
    const int lane = tid & 31;

    if (bid < NCOEFF) {
        // ================= COEFF =================
        const int b = bid / 65;
        const int o = bid - b * 65;

        if (o == 64) {
            for (int i = tid; i < 512; i += 128) w1s[i] = W1[i];
            for (int i = tid; i < 224; i += 128) w2s[i] = W2[i];
            __syncthreads();
            #pragma unroll
            for (int cc = 0; cc < 2; cc++) {
                const int c = tid + cc * 128;
                float p[T_];
                const float4* pp = reinterpret_cast<const float4*>(d_pooled + (b * C_ + c) * T_);
                #pragma unroll
                for (int q = 0; q < 4; q++) {
                    float4 v = pp[q];
                    p[q*4+0]=v.x; p[q*4+1]=v.y; p[q*4+2]=v.z; p[q*4+3]=v.w;
                }
                float s[KSZ];
                #pragma unroll
                for (int k = 0; k < KSZ; k++) s[k] = 0.f;
                for (int u = 0; u < 32; u++) {
                    float acc = 0.f;
                    #pragma unroll
                    for (int t = 0; t < T_; t++) acc += p[t] * w1s[u * 16 + t];
                    float g = tanhf(acc);
                    #pragma unroll
                    for (int k = 0; k < KSZ; k++) s[k] += g * w2s[k * 32 + u];
                }
                float m = s[0];
                #pragma unroll
                for (int k = 1; k < KSZ; k++) m = fmaxf(m, s[k]);
                float e[KSZ], sum = 0.f;
                #pragma unroll
                for (int k = 0; k < KSZ; k++) { e[k] = expf(s[k] - m); sum += e[k]; }
                float inv = 1.0f / sum;
                #pragma unroll
                for (int k = 0; k < KSZ; k++)
                    d_Kern[(b * C_ + c) * KSZ + k] = e[k] * inv;
            }
        } else {
            for (int i = tid; i < C_ * PSROW; i += 128) smf[i] = 0.f;
            __syncthreads();
            const float4* pp = reinterpret_cast<const float4*>(d_pooled + b * C_ * T_);
            for (int i = tid; i < C_ * T_ / 4; i += 128) {
                float4 v = pp[i];
                int e0 = i * 4;
                int c = e0 >> 4, t = e0 & 15;
                float* rr = &smf[c * PSROW + PAD + t];
                rr[0] = v.x; rr[1] = v.y; rr[2] = v.z; rr[3] = v.w;
            }
            __syncthreads();

            float acc[T_];
            #pragma unroll
            for (int t = 0; t < T_; t++) acc[t] = 0.f;
            const float* w = Wl1 + o * (C_ * KSZ);
            #pragma unroll
            for (int ii = 0; ii < 2; ii++) {
                const int i = tid * 2 + ii;
                float wk[KSZ];
                #pragma unroll
                for (int k = 0; k < KSZ; k++) wk[k] = w[i * KSZ + k];
                float pv[T_ + 2 * PAD];
                #pragma unroll
                for (int j = 0; j < T_ + 2 * PAD; j++) pv[j] = smf[i * PSROW + j];
                #pragma unroll
                for (int t = 0; t < T_; t++) {
                    #pragma unroll
                    for (int k = 0; k < KSZ; k++)
                        acc[t] += wk[k] * pv[t + k];
                }
            }
            #pragma unroll
            for (int off = 16; off > 0; off >>= 1) {
                #pragma unroll
                for (int t = 0; t < T_; t++)
                    acc[t] += __shfl_xor_sync(0xffffffffu, acc[t], off);
            }
            if (lane == 0) {
                #pragma unroll
                for (int t = 0; t < T_; t++) redp[warp * T_ + t] = acc[t];
            }
            __syncthreads();
            if (tid < T_) {
                float s = redp[0*T_+tid] + redp[1*T_+tid] + redp[2*T_+tid] + redp[3*T_+tid];
                d_Yt[(b * T_ + tid) * 64 + o] = tanhf(s);
            }
        }
        __threadfence();
        __syncthreads();
        if (tid == 0) atomicAdd(&d_cdone[b], 1);
        return;
    }

    // ================= MAIN half-slice tile =================
    const int id   = bid - NCOEFF;      // 0..4095
    const int b    = id >> 9;           // /512
    const int r    = id & 511;
    const int c    = r >> 1;
    const int half = r & 1;
    const int bc   = b * C_ + c;

    const size_t row0 = (size_t)(b * T_ * C_ + c);
    const size_t goff = row0 * HW_ + half * (HHW4 * 4);

    if (tid == 0) MBAR_INIT(mbar, 1);
    __syncthreads();
    if (tid == 0) {
        // issue all x loads FIRST — overlaps coeff compute; batch 0's x is
        // freshest in L2 thanks to the reversed pool order
        MBAR_EXPECT(mbar, (uint32_t)(T_ * HBYTES));
        #pragma unroll
        for (int t = 0; t < T_; t++)
            BULK_G2S(s_base + t * HBYTES,
                     x + goff + (size_t)t * (C_ * HW_),
                     (uint32_t)HBYTES, mbar);
        while (((volatile int*)d_cdone)[b] < 65) __nanosleep(64);
        __threadfence();
    }
    __syncthreads();

    if (tid < T_) {
        const float4* wv = reinterpret_cast<const float4*>(Wl2 + c * 64);
        const float4* yv = reinterpret_cast<const float4*>(d_Yt + (b * T_ + tid) * 64);
        float acc = 0.f;
        #pragma unroll
        for (int q = 0; q < 16; q++) {
            float4 wq = wv[q], yq = yv[q];
            acc += wq.x * yq.x + wq.y * yq.y + wq.z * yq.z + wq.w * yq.w;
        }
        lrs[tid] = 1.0f / (1.0f + expf(-acc));
    }
    float kr[KSZ];
    #pragma unroll
    for (int k = 0; k < KSZ; k++) kr[k] = d_Kern[bc * KSZ + k];
    __syncthreads();

    MBAR_WAIT(mbar, 0);

    if (tid < HHW4) {
        float4 g[T_];
        #pragma unroll
        for (int t = 0; t < T_; t++) {
            float4 v = sm4[t * HHW4 + tid];
            float l = lrs[t];
            g[t].x = v.x * l; g[t].y = v.y * l; g[t].z = v.z * l; g[t].w = v.w * l;
        }
        #pragma unroll
        for (int t = 0; t < T_; t++) {
            float4 a; a.x = a.y = a.z = a.w = 0.f;
            #pragma unroll
            for (int k = 0; k < KSZ; k++) {
                int u = t + k - PAD;
                if (u >= 0 && u < T_) {          // constant-folded
                    float kk = kr[k];
                    a.x += kk * g[u].x;
                    a.y += kk * g[u].y;
                    a.z += kk * g[u].z;
                    a.w += kk * g[u].w;
                }
            }
            sm4[t * HHW4 + tid] = a;
        }
    }
    __syncthreads();
    if (tid == 0) {
        FENCE_ASYNC();
        #pragma unroll
        for (int t = 0; t < T_; t++)
            BULK_S2G(out + goff + (size_t)t * (C_ * HW_),
                     s_base + t * HBYTES, (uint32_t)HBYTES);
        BULK_COMMIT();
        BULK_WAIT0();
    }
    __syncthreads();   // load-bearing: no thread exits with bulk stores in flight
}

// ---------------------------------------------------------------------------
extern "C" void kernel_launch(void* const* d_in, const int* in_sizes, int n_in,
                              void* d_out, int out_size) {
    const float* x   = (const float*)d_in[0];
    const float* W1  = (const float*)d_in[1];
    const float* W2  = (const float*)d_in[2];
    const float* Wl1 = (const float*)d_in[3];
    const float* Wl2 = (const float*)d_in[4];
    float* out = (float*)d_out;

    static bool attr_done = false;
    if (!attr_done) {
        cudaFuncSetAttribute(pool_kernel,
            cudaFuncAttributeMaxDynamicSharedMemorySize, POOL_SMEM);
        cudaFuncSetAttribute(fused_kernel,
            cudaFuncAttributeMaxDynamicSharedMemorySize, DYN_SMEM);
        attr_done = true;
    }

    pool_kernel<<<NPOOLBLK, 256, POOL_SMEM>>>(x);
    fused_kernel<<<NCOEFF + NMAIN, 128, DYN_SMEM>>>(x, out, W1, W2, Wl1, Wl2);
}